// round 10
// baseline (speedup 1.0000x reference)
#include <cuda_runtime.h>
#include <cuda_bf16.h>
#include <cstdint>

// ---------------------------------------------------------------------------
// Problem constants
// ---------------------------------------------------------------------------
#define BATCH    131072
#define NCH      6
#define RES_DIM  100
#define CF_K     0.02f
#define TILE_M   128
#define THREADS  256
#define NTILES   (BATCH / TILE_M)     // 1024
#define CTAS_PER_CH 24
#define GRID_MLP (NCH * CTAS_PER_CH)  // 144

// bf16 tile k-stride: 136 elements = 272 bytes (word stride 68 == 4 mod 32 ->
// LDSM 8-row phases cover all 32 banks exactly once; stores conflict-free)
#define KSTR_B   272

// ---------------------------------------------------------------------------
// SMEM layout (bytes)
// ---------------------------------------------------------------------------
#define AH_OFF   0                        // A hi : 128 x 136 bf16 = 34816
#define AL_OFF   34816                    // A lo
#define B1H_OFF  69632                    // W1^T hi : 128 x 136
#define B1L_OFF  104448
#define B2H_OFF  139264                   // W2^T hi : 64 x 136 = 17408
#define B2L_OFF  156672
#define B3H_OFF  174080                   // W3^T hi : 32 x 136 = 8704
#define B3L_OFF  182784
#define MISC_B1  191488                   // 128 f32
#define MISC_B2  192000                   // 64 f32
#define MISC_B3  192256                   // 32 f32
#define MISC_W4  192384                   // 32 f32
#define MISC_CD  192512                   // 36 f32 (decay*coupling*CF_K)
#define MISC_FLG 192656                   // 1 u32 (finisher flag)
#define SMEM_BYTES 192768
// L3 epilogue reuses AH region as fp32 H3 scratch, stride 33 floats
#define H3_STRIDE 33

// per-tile arrival counters (device global scratch; self-resetting)
__device__ unsigned int g_tile_cnt[NTILES];

// ---------------------------------------------------------------------------
// Helpers
// ---------------------------------------------------------------------------
__device__ __forceinline__ float sigmoidf_fast(float x) {
    return __fdividef(1.0f, 1.0f + __expf(-x));
}
__device__ __forceinline__ float siluf(float x) { return x * sigmoidf_fast(x); }

__device__ __forceinline__ void split_bf(float x, uint16_t& h, uint16_t& l) {
    __nv_bfloat16 hb = __float2bfloat16(x);
    float r = x - __bfloat162float(hb);
    __nv_bfloat16 lb = __float2bfloat16(r);
    h = *(uint16_t*)&hb;  l = *(uint16_t*)&lb;
}

// one m16n8k16 bf16 MMA, fp32 accum (plain sm_80+ PTX -> HMMA on sm_103a)
__device__ __forceinline__ void mma16816(float c[4],
                                         uint32_t a0, uint32_t a1, uint32_t a2, uint32_t a3,
                                         uint32_t b0, uint32_t b1) {
    asm volatile(
        "mma.sync.aligned.m16n8k16.row.col.f32.bf16.bf16.f32 "
        "{%0,%1,%2,%3}, {%4,%5,%6,%7}, {%8,%9}, {%0,%1,%2,%3};"
        : "+f"(c[0]), "+f"(c[1]), "+f"(c[2]), "+f"(c[3])
        : "r"(a0), "r"(a1), "r"(a2), "r"(a3), "r"(b0), "r"(b1));
}

__device__ __forceinline__ void ldsm_x4(uint32_t& r0, uint32_t& r1,
                                        uint32_t& r2, uint32_t& r3, uint32_t addr) {
    asm volatile("ldmatrix.sync.aligned.m8n8.x4.shared.b16 {%0,%1,%2,%3}, [%4];"
                 : "=r"(r0), "=r"(r1), "=r"(r2), "=r"(r3) : "r"(addr));
}

// ---------------------------------------------------------------------------
// Layer MMA with ldmatrix fragments.
//   Warp computes [32 x NBLK*8]; acc[mb*NBLK+nb][4].
//   A row-major k-contig at aH/aL, B = W^T[n][k] at bH/bL.
//   3 products: Ah*Bh + Ah*Bl + Al*Bh.
// ---------------------------------------------------------------------------
template<int NBLK, int KSTEPS>
__device__ __forceinline__ void layer_mma(uint32_t sb,
                                          int aH, int aL, int bH, int bL,
                                          int mbase, int nbase, int lane,
                                          float (*acc)[4])
{
    #pragma unroll
    for (int i = 0; i < 2 * NBLK; i++)
        #pragma unroll
        for (int j = 0; j < 4; j++) acc[i][j] = 0.0f;

    // A lane address: row = mbase + mb*16 + (lane&15); +16B for k-hi half
    const uint32_t aRow = (uint32_t)(mbase + (lane & 15)) * KSTR_B + ((lane >> 4) << 4);
    const uint32_t aH0 = sb + aH + aRow;
    const uint32_t aL0 = sb + aL + aRow;
    // B lane address (x4 covers nb pair): n = nbase + j*16 + ((lane&16)?8:0) + (lane&7)
    const uint32_t bRow = (uint32_t)(nbase + ((lane & 16) >> 1) + (lane & 7)) * KSTR_B
                        + ((lane & 8) << 1);
    const uint32_t bH0 = sb + bH + bRow;
    const uint32_t bL0 = sb + bL + bRow;

    #pragma unroll
    for (int ks = 0; ks < KSTEPS; ks++) {
        const uint32_t ko = (uint32_t)ks * 32u;
        uint32_t ah[2][4], al[2][4];
        ldsm_x4(ah[0][0], ah[0][1], ah[0][2], ah[0][3], aH0 + ko);
        ldsm_x4(ah[1][0], ah[1][1], ah[1][2], ah[1][3], aH0 + 16 * KSTR_B + ko);
        ldsm_x4(al[0][0], al[0][1], al[0][2], al[0][3], aL0 + ko);
        ldsm_x4(al[1][0], al[1][1], al[1][2], al[1][3], aL0 + 16 * KSTR_B + ko);

        #pragma unroll
        for (int j = 0; j < NBLK / 2; j++) {
            uint32_t bh0, bh1, bh2, bh3, bl0, bl1, bl2, bl3;
            ldsm_x4(bh0, bh1, bh2, bh3, bH0 + (uint32_t)j * 16 * KSTR_B + ko);
            ldsm_x4(bl0, bl1, bl2, bl3, bL0 + (uint32_t)j * 16 * KSTR_B + ko);
            #pragma unroll
            for (int mb = 0; mb < 2; mb++) {
                float* c0 = acc[mb * NBLK + 2 * j];
                float* c1 = acc[mb * NBLK + 2 * j + 1];
                mma16816(c0, ah[mb][0], ah[mb][1], ah[mb][2], ah[mb][3], bh0, bh1);
                mma16816(c0, ah[mb][0], ah[mb][1], ah[mb][2], ah[mb][3], bl0, bl1);
                mma16816(c0, al[mb][0], al[mb][1], al[mb][2], al[mb][3], bh0, bh1);
                mma16816(c1, ah[mb][0], ah[mb][1], ah[mb][2], ah[mb][3], bh2, bh3);
                mma16816(c1, ah[mb][0], ah[mb][1], ah[mb][2], ah[mb][3], bl2, bl3);
                mma16816(c1, al[mb][0], al[mb][1], al[mb][2], al[mb][3], bh2, bh3);
            }
        }
    }
}

// Epilogue: bias + silu, re-split to bf16 hi/lo, store into A tiles.
template<int NBLK>
__device__ __forceinline__ void epi_store_bf(char* smem, int biasOff,
                                             int mbase, int nbase, int g, int t,
                                             float (*acc)[4])
{
    #pragma unroll
    for (int mb = 0; mb < 2; mb++) {
        #pragma unroll
        for (int nb = 0; nb < NBLK; nb++) {
            const float* c = acc[mb * NBLK + nb];
            int col = nbase + nb * 8 + 2 * t;
            float bb0 = *(const float*)(smem + biasOff + col * 4);
            float bb1 = *(const float*)(smem + biasOff + (col + 1) * 4);
            int r0 = mbase + mb * 16 + g;
            float x0 = siluf(c[0] + bb0), x1 = siluf(c[1] + bb1);
            float y0 = siluf(c[2] + bb0), y1 = siluf(c[3] + bb1);
            uint16_t h0,l0,h1,l1;
            split_bf(x0, h0, l0); split_bf(x1, h1, l1);
            *(uint32_t*)(smem + AH_OFF + r0 * KSTR_B + col * 2) = (uint32_t)h1 << 16 | h0;
            *(uint32_t*)(smem + AL_OFF + r0 * KSTR_B + col * 2) = (uint32_t)l1 << 16 | l0;
            split_bf(y0, h0, l0); split_bf(y1, h1, l1);
            *(uint32_t*)(smem + AH_OFF + (r0+8) * KSTR_B + col * 2) = (uint32_t)h1 << 16 | h0;
            *(uint32_t*)(smem + AL_OFF + (r0+8) * KSTR_B + col * 2) = (uint32_t)l1 << 16 | l0;
        }
    }
}

// ---------------------------------------------------------------------------
// Fused kernel: persistent HMMA MLP + per-tile coupled fixed-point finisher
// ---------------------------------------------------------------------------
__global__ __launch_bounds__(THREADS, 1)
void chambers_fused(const float* __restrict__ res,
                    const float* __restrict__ W1, const float* __restrict__ b1,
                    const float* __restrict__ W2, const float* __restrict__ b2,
                    const float* __restrict__ W3, const float* __restrict__ b3,
                    const float* __restrict__ W4, const float* __restrict__ b4,
                    const float* __restrict__ coupling,
                    const float* __restrict__ decay,
                    float* __restrict__ act, float* __restrict__ rawOut)
{
    extern __shared__ char smem[];
    const uint32_t sb = (uint32_t)__cvta_generic_to_shared(smem);
    const int tid  = threadIdx.x;
    const int w    = tid >> 5;
    const int lane = tid & 31;
    const int g    = lane >> 2;
    const int t    = lane & 3;
    const int c    = blockIdx.x / CTAS_PER_CH;
    const int slot = blockIdx.x % CTAS_PER_CH;

    // ---- stage weights once: W^T[n][k] bf16 hi/lo, k-stride 136 -----------
    {
        const float* W1g = W1 + c * 12800;
        for (int i = tid; i < 128 * 112; i += THREADS) {
            int n = i / 112, k = i - n * 112;
            float x = (k < RES_DIM) ? W1g[k * 128 + n] : 0.0f;
            uint16_t h, l; split_bf(x, h, l);
            *(uint16_t*)(smem + B1H_OFF + n * KSTR_B + k * 2) = h;
            *(uint16_t*)(smem + B1L_OFF + n * KSTR_B + k * 2) = l;
        }
        const float* W2g = W2 + c * 8192;
        for (int i = tid; i < 64 * 128; i += THREADS) {
            int n = i >> 7, k = i & 127;
            uint16_t h, l; split_bf(W2g[k * 64 + n], h, l);
            *(uint16_t*)(smem + B2H_OFF + n * KSTR_B + k * 2) = h;
            *(uint16_t*)(smem + B2L_OFF + n * KSTR_B + k * 2) = l;
        }
        const float* W3g = W3 + c * 2048;
        for (int i = tid; i < 32 * 64; i += THREADS) {
            int n = i >> 6, k = i & 63;
            uint16_t h, l; split_bf(W3g[k * 32 + n], h, l);
            *(uint16_t*)(smem + B3H_OFF + n * KSTR_B + k * 2) = h;
            *(uint16_t*)(smem + B3L_OFF + n * KSTR_B + k * 2) = l;
        }
        if (tid < 128) *(float*)(smem + MISC_B1 + tid * 4) = b1[c * 128 + tid];
        if (tid < 64)  *(float*)(smem + MISC_B2 + tid * 4) = b2[c * 64 + tid];
        if (tid < 32)  *(float*)(smem + MISC_B3 + tid * 4) = b3[c * 32 + tid];
        if (tid < 32)  *(float*)(smem + MISC_W4 + tid * 4) = W4[c * 32 + tid];
        if (tid < NCH * NCH) {
            int cc = tid / NCH;
            *(float*)(smem + MISC_CD + tid * 4) = decay[cc] * coupling[tid] * CF_K;
        }
    }
    const float b4c = b4[c];
    __syncthreads();

    const int mbase = (w & 3) * 32;

    for (int tix = slot; tix < NTILES; tix += CTAS_PER_CH) {
        // ---- stage A = res tile fp32 -> bf16 hi/lo, K padded to 112 -------
        {
            const float* rb = res + (size_t)tix * TILE_M * RES_DIM;
            for (int i = tid; i < 128 * 32; i += THREADS) {
                int r = i >> 5, c4 = i & 31;
                if (c4 >= 28) continue;
                float4 v = make_float4(0.f, 0.f, 0.f, 0.f);
                if (c4 < 25) v = *(const float4*)(rb + r * RES_DIM + c4 * 4);
                uint16_t h0,l0,h1,l1,h2,l2,h3,l3;
                split_bf(v.x,h0,l0); split_bf(v.y,h1,l1);
                split_bf(v.z,h2,l2); split_bf(v.w,h3,l3);
                *(uint2*)(smem + AH_OFF + r * KSTR_B + c4 * 8) =
                    make_uint2((uint32_t)h1 << 16 | h0, (uint32_t)h3 << 16 | h2);
                *(uint2*)(smem + AL_OFF + r * KSTR_B + c4 * 8) =
                    make_uint2((uint32_t)l1 << 16 | l0, (uint32_t)l3 << 16 | l2);
            }
        }
        __syncthreads();

        // ---- Layer 1: [128x112] @ W1 -> 128x128, silu ---------------------
        {
            float acc[16][4];
            layer_mma<8, 7>(sb, AH_OFF, AL_OFF, B1H_OFF, B1L_OFF,
                            mbase, (w >> 2) * 64, lane, acc);
            __syncthreads();
            epi_store_bf<8>(smem, MISC_B1, mbase, (w >> 2) * 64, g, t, acc);
        }
        __syncthreads();

        // ---- Layer 2: [128x128] @ W2 -> 128x64, silu ----------------------
        {
            float acc[8][4];
            layer_mma<4, 8>(sb, AH_OFF, AL_OFF, B2H_OFF, B2L_OFF,
                            mbase, (w >> 2) * 32, lane, acc);
            __syncthreads();
            epi_store_bf<4>(smem, MISC_B2, mbase, (w >> 2) * 32, g, t, acc);
        }
        __syncthreads();

        // ---- Layer 3: [128x64] @ W3 -> 128x32, silu (fp32 scratch) --------
        {
            float acc[4][4];
            layer_mma<2, 4>(sb, AH_OFF, AL_OFF, B3H_OFF, B3L_OFF,
                            mbase, (w >> 2) * 16, lane, acc);
            __syncthreads();   // all warps done reading A before fp32 overwrite
            float* h3 = (float*)(smem + AH_OFF);
            const int nbase = (w >> 2) * 16;
            #pragma unroll
            for (int mb = 0; mb < 2; mb++) {
                #pragma unroll
                for (int nb = 0; nb < 2; nb++) {
                    const float* cc = acc[mb * 2 + nb];
                    int col = nbase + nb * 8 + 2 * t;
                    float bb0 = *(const float*)(smem + MISC_B3 + col * 4);
                    float bb1 = *(const float*)(smem + MISC_B3 + (col + 1) * 4);
                    int r0 = mbase + mb * 16 + g;
                    h3[r0 * H3_STRIDE + col]       = siluf(cc[0] + bb0);
                    h3[r0 * H3_STRIDE + col + 1]   = siluf(cc[1] + bb1);
                    h3[(r0+8) * H3_STRIDE + col]   = siluf(cc[2] + bb0);
                    h3[(r0+8) * H3_STRIDE + col+1] = siluf(cc[3] + bb1);
                }
            }
        }
        __syncthreads();

        // ---- Layer 4: dot with W4 -> raw ----------------------------------
        if (tid < TILE_M) {
            const float* h3 = (const float*)(smem + AH_OFF) + tid * H3_STRIDE;
            float accv = b4c;
            #pragma unroll
            for (int h = 0; h < 32; h++)
                accv = fmaf(h3[h], *(const float*)(smem + MISC_W4 + h * 4), accv);
            rawOut[(size_t)(tix * TILE_M + tid) * NCH + c] = accv;
        }
        __syncthreads();

        // ---- arrival counter: 6th chamber CTA runs the coupled iteration --
        if (tid == 0) {
            __threadfence();
            unsigned old = atomicAdd(&g_tile_cnt[tix], 1u);
            *(unsigned*)(smem + MISC_FLG) = old;
        }
        __syncthreads();
        if (*(volatile unsigned*)(smem + MISC_FLG) == 5u) {
            __threadfence();   // acquire: see all 6 chambers' raw writes
            if (tid < TILE_M) {
                size_t b = (size_t)tix * TILE_M + tid;
                const float* rp = rawOut + b * NCH;
                float r[NCH], a[NCH];
                #pragma unroll
                for (int j = 0; j < NCH; j++) r[j] = rp[j];
                #pragma unroll
                for (int j = 0; j < NCH; j++) a[j] = sigmoidf_fast(r[j]);
                #pragma unroll
                for (int it = 0; it < 5; it++) {
                    float d[NCH];
                    #pragma unroll
                    for (int j = 0; j < NCH; j++) d[j] = 0.0f;
                    #pragma unroll
                    for (int cc = 0; cc < NCH; cc++)
                        #pragma unroll
                        for (int j = 0; j < NCH; j++)
                            d[j] = fmaf(a[cc],
                                        *(const float*)(smem + MISC_CD + (cc * NCH + j) * 4),
                                        d[j]);
                    #pragma unroll
                    for (int j = 0; j < NCH; j++) a[j] = sigmoidf_fast(r[j] + d[j]);
                }
                float* ap = act + b * NCH;
                #pragma unroll
                for (int j = 0; j < NCH; j++) ap[j] = a[j];
            }
            __syncthreads();
            if (tid == 0) atomicExch(&g_tile_cnt[tix], 0u);   // reset for next replay
        }
        __syncthreads();   // protect A region before next tile staging
    }
}

// ---------------------------------------------------------------------------
// Launch: single fused kernel
// ---------------------------------------------------------------------------
extern "C" void kernel_launch(void* const* d_in, const int* in_sizes, int n_in,
                              void* d_out, int out_size)
{
    const float* res      = (const float*)d_in[0];
    const float* W1       = (const float*)d_in[1];
    const float* b1       = (const float*)d_in[2];
    const float* W2       = (const float*)d_in[3];
    const float* b2       = (const float*)d_in[4];
    const float* W3       = (const float*)d_in[5];
    const float* b3       = (const float*)d_in[6];
    const float* W4       = (const float*)d_in[7];
    const float* b4       = (const float*)d_in[8];
    const float* coupling = (const float*)d_in[9];
    const float* decay    = (const float*)d_in[10];

    float* out = (float*)d_out;
    float* act = out;                          // [B, 6]
    float* raw = out + (size_t)BATCH * NCH;    // [B, 6]

    cudaFuncSetAttribute(chambers_fused,
                         cudaFuncAttributeMaxDynamicSharedMemorySize, SMEM_BYTES);

    chambers_fused<<<GRID_MLP, THREADS, SMEM_BYTES>>>(
        res, W1, b1, W2, b2, W3, b3, W4, b4, coupling, decay, act, raw);
}

// round 11
// speedup vs baseline: 1.2760x; 1.2760x over previous
#include <cuda_runtime.h>
#include <cuda_bf16.h>
#include <cstdint>

// ---------------------------------------------------------------------------
// Problem constants
// ---------------------------------------------------------------------------
#define BATCH    131072
#define NCH      6
#define RES_DIM  100
#define CF_K     0.02f
#define TILE_M   128
#define THREADS  512
#define NTILES   (BATCH / TILE_M)     // 1024
#define CTAS_PER_CH 24
#define GRID_MLP (NCH * CTAS_PER_CH)  // 144

// bf16 tile k-stride: 136 elements = 272 bytes (word stride 68 == 4 mod 32 ->
// LDSM 8-row phases cover all 32 banks exactly once; stores conflict-free)
#define KSTR_B   272

// ---------------------------------------------------------------------------
// SMEM layout (bytes)
// ---------------------------------------------------------------------------
#define AH_OFF   0                        // A hi : 128 x 136 bf16 = 34816
#define AL_OFF   34816                    // A lo
#define B1H_OFF  69632                    // W1^T hi : 128 x 136
#define B1L_OFF  104448
#define B2H_OFF  139264                   // W2^T hi : 64 x 136 = 17408
#define B2L_OFF  156672
#define B3H_OFF  174080                   // W3^T hi : 32 x 136 = 8704
#define B3L_OFF  182784
#define MISC_B1  191488                   // 128 f32
#define MISC_B2  192000                   // 64 f32
#define MISC_B3  192256                   // 32 f32
#define MISC_W4  192384                   // 32 f32
#define SMEM_BYTES 192512
// L3 epilogue reuses AH region as fp32 H3 scratch, stride 33 floats
#define H3_STRIDE 33

// ---------------------------------------------------------------------------
// Helpers
// ---------------------------------------------------------------------------
__device__ __forceinline__ float sigmoidf_fast(float x) {
    return __fdividef(1.0f, 1.0f + __expf(-x));
}
__device__ __forceinline__ float siluf(float x) { return x * sigmoidf_fast(x); }

__device__ __forceinline__ void split_bf(float x, uint16_t& h, uint16_t& l) {
    __nv_bfloat16 hb = __float2bfloat16(x);
    float r = x - __bfloat162float(hb);
    __nv_bfloat16 lb = __float2bfloat16(r);
    h = *(uint16_t*)&hb;  l = *(uint16_t*)&lb;
}

// one m16n8k16 bf16 MMA, fp32 accum (plain sm_80+ PTX -> HMMA on sm_103a)
__device__ __forceinline__ void mma16816(float c[4],
                                         uint32_t a0, uint32_t a1, uint32_t a2, uint32_t a3,
                                         uint32_t b0, uint32_t b1) {
    asm volatile(
        "mma.sync.aligned.m16n8k16.row.col.f32.bf16.bf16.f32 "
        "{%0,%1,%2,%3}, {%4,%5,%6,%7}, {%8,%9}, {%0,%1,%2,%3};"
        : "+f"(c[0]), "+f"(c[1]), "+f"(c[2]), "+f"(c[3])
        : "r"(a0), "r"(a1), "r"(a2), "r"(a3), "r"(b0), "r"(b1));
}

__device__ __forceinline__ void ldsm_x4(uint32_t& r0, uint32_t& r1,
                                        uint32_t& r2, uint32_t& r3, uint32_t addr) {
    asm volatile("ldmatrix.sync.aligned.m8n8.x4.shared.b16 {%0,%1,%2,%3}, [%4];"
                 : "=r"(r0), "=r"(r1), "=r"(r2), "=r"(r3) : "r"(addr));
}

// ---------------------------------------------------------------------------
// Layer MMA with ldmatrix fragments.
//   Warp computes [MBLK*16 x NBLK*8]; acc[mb*NBLK+nb][4].
//   A row-major k-contig at aH/aL, B = W^T[n][k] at bH/bL.
//   3 products: Ah*Bh + Ah*Bl + Al*Bh.   NBLK must be even.
// ---------------------------------------------------------------------------
template<int MBLK, int NBLK, int KSTEPS>
__device__ __forceinline__ void layer_mma(uint32_t sb,
                                          int aH, int aL, int bH, int bL,
                                          int mbase, int nbase, int lane,
                                          float (*acc)[4])
{
    #pragma unroll
    for (int i = 0; i < MBLK * NBLK; i++)
        #pragma unroll
        for (int j = 0; j < 4; j++) acc[i][j] = 0.0f;

    // A lane address: row = mbase + mb*16 + (lane&15); +16B for k-hi half
    const uint32_t aRow = (uint32_t)(mbase + (lane & 15)) * KSTR_B + ((lane >> 4) << 4);
    const uint32_t aH0 = sb + aH + aRow;
    const uint32_t aL0 = sb + aL + aRow;
    // B lane address (x4 covers an n-block pair): n = nbase + ((lane&16)?8:0) + (lane&7)
    const uint32_t bRow = (uint32_t)(nbase + ((lane & 16) >> 1) + (lane & 7)) * KSTR_B
                        + ((lane & 8) << 1);
    const uint32_t bH0 = sb + bH + bRow;
    const uint32_t bL0 = sb + bL + bRow;

    #pragma unroll
    for (int ks = 0; ks < KSTEPS; ks++) {
        const uint32_t ko = (uint32_t)ks * 32u;
        uint32_t ah[MBLK][4], al[MBLK][4];
        #pragma unroll
        for (int mb = 0; mb < MBLK; mb++) {
            ldsm_x4(ah[mb][0], ah[mb][1], ah[mb][2], ah[mb][3],
                    aH0 + (uint32_t)mb * 16 * KSTR_B + ko);
            ldsm_x4(al[mb][0], al[mb][1], al[mb][2], al[mb][3],
                    aL0 + (uint32_t)mb * 16 * KSTR_B + ko);
        }

        #pragma unroll
        for (int j = 0; j < NBLK / 2; j++) {
            uint32_t bh0, bh1, bh2, bh3, bl0, bl1, bl2, bl3;
            ldsm_x4(bh0, bh1, bh2, bh3, bH0 + (uint32_t)j * 16 * KSTR_B + ko);
            ldsm_x4(bl0, bl1, bl2, bl3, bL0 + (uint32_t)j * 16 * KSTR_B + ko);
            #pragma unroll
            for (int mb = 0; mb < MBLK; mb++) {
                float* c0 = acc[mb * NBLK + 2 * j];
                float* c1 = acc[mb * NBLK + 2 * j + 1];
                mma16816(c0, ah[mb][0], ah[mb][1], ah[mb][2], ah[mb][3], bh0, bh1);
                mma16816(c0, ah[mb][0], ah[mb][1], ah[mb][2], ah[mb][3], bl0, bl1);
                mma16816(c0, al[mb][0], al[mb][1], al[mb][2], al[mb][3], bh0, bh1);
                mma16816(c1, ah[mb][0], ah[mb][1], ah[mb][2], ah[mb][3], bh2, bh3);
                mma16816(c1, ah[mb][0], ah[mb][1], ah[mb][2], ah[mb][3], bl2, bl3);
                mma16816(c1, al[mb][0], al[mb][1], al[mb][2], al[mb][3], bh2, bh3);
            }
        }
    }
}

// Epilogue: bias + silu, re-split to bf16 hi/lo, store into A tiles.
template<int MBLK, int NBLK>
__device__ __forceinline__ void epi_store_bf(char* smem, int biasOff,
                                             int mbase, int nbase, int g, int t,
                                             float (*acc)[4])
{
    #pragma unroll
    for (int mb = 0; mb < MBLK; mb++) {
        #pragma unroll
        for (int nb = 0; nb < NBLK; nb++) {
            const float* c = acc[mb * NBLK + nb];
            int col = nbase + nb * 8 + 2 * t;
            float bb0 = *(const float*)(smem + biasOff + col * 4);
            float bb1 = *(const float*)(smem + biasOff + (col + 1) * 4);
            int r0 = mbase + mb * 16 + g;
            float x0 = siluf(c[0] + bb0), x1 = siluf(c[1] + bb1);
            float y0 = siluf(c[2] + bb0), y1 = siluf(c[3] + bb1);
            uint16_t h0,l0,h1,l1;
            split_bf(x0, h0, l0); split_bf(x1, h1, l1);
            *(uint32_t*)(smem + AH_OFF + r0 * KSTR_B + col * 2) = (uint32_t)h1 << 16 | h0;
            *(uint32_t*)(smem + AL_OFF + r0 * KSTR_B + col * 2) = (uint32_t)l1 << 16 | l0;
            split_bf(y0, h0, l0); split_bf(y1, h1, l1);
            *(uint32_t*)(smem + AH_OFF + (r0+8) * KSTR_B + col * 2) = (uint32_t)h1 << 16 | h0;
            *(uint32_t*)(smem + AL_OFF + (r0+8) * KSTR_B + col * 2) = (uint32_t)l1 << 16 | l0;
        }
    }
}

// ---------------------------------------------------------------------------
// MLP kernel: persistent, HMMA bf16 split-precision, 16 warps/CTA
// ---------------------------------------------------------------------------
__global__ __launch_bounds__(THREADS, 1)
void chambers_mlp_hmma(const float* __restrict__ res,
                       const float* __restrict__ W1, const float* __restrict__ b1,
                       const float* __restrict__ W2, const float* __restrict__ b2,
                       const float* __restrict__ W3, const float* __restrict__ b3,
                       const float* __restrict__ W4, const float* __restrict__ b4,
                       float* __restrict__ rawOut)
{
    extern __shared__ char smem[];
    const uint32_t sb = (uint32_t)__cvta_generic_to_shared(smem);
    const int tid  = threadIdx.x;
    const int w    = tid >> 5;
    const int lane = tid & 31;
    const int g    = lane >> 2;
    const int t    = lane & 3;
    const int c    = blockIdx.x / CTAS_PER_CH;
    const int slot = blockIdx.x % CTAS_PER_CH;

    // ---- stage weights once: W^T[n][k] bf16 hi/lo, k-stride 136 -----------
    {
        const float* W1g = W1 + c * 12800;
        for (int i = tid; i < 128 * 112; i += THREADS) {
            int n = i / 112, k = i - n * 112;
            float x = (k < RES_DIM) ? W1g[k * 128 + n] : 0.0f;
            uint16_t h, l; split_bf(x, h, l);
            *(uint16_t*)(smem + B1H_OFF + n * KSTR_B + k * 2) = h;
            *(uint16_t*)(smem + B1L_OFF + n * KSTR_B + k * 2) = l;
        }
        const float* W2g = W2 + c * 8192;
        for (int i = tid; i < 64 * 128; i += THREADS) {
            int n = i >> 7, k = i & 127;
            uint16_t h, l; split_bf(W2g[k * 64 + n], h, l);
            *(uint16_t*)(smem + B2H_OFF + n * KSTR_B + k * 2) = h;
            *(uint16_t*)(smem + B2L_OFF + n * KSTR_B + k * 2) = l;
        }
        const float* W3g = W3 + c * 2048;
        for (int i = tid; i < 32 * 64; i += THREADS) {
            int n = i >> 6, k = i & 63;
            uint16_t h, l; split_bf(W3g[k * 32 + n], h, l);
            *(uint16_t*)(smem + B3H_OFF + n * KSTR_B + k * 2) = h;
            *(uint16_t*)(smem + B3L_OFF + n * KSTR_B + k * 2) = l;
        }
        if (tid < 128) *(float*)(smem + MISC_B1 + tid * 4) = b1[c * 128 + tid];
        if (tid < 64)  *(float*)(smem + MISC_B2 + tid * 4) = b2[c * 64 + tid];
        if (tid < 32)  *(float*)(smem + MISC_B3 + tid * 4) = b3[c * 32 + tid];
        if (tid < 32)  *(float*)(smem + MISC_W4 + tid * 4) = W4[c * 32 + tid];
    }
    const float b4c = b4[c];
    __syncthreads();

    const int mbase  = (w & 3) * 32;      // layers 1-2: 4 m-groups x 32 rows
    const int mbase3 = (w & 7) * 16;      // layer 3: 8 m-groups x 16 rows

    for (int tix = slot; tix < NTILES; tix += CTAS_PER_CH) {
        // ---- stage A = res tile fp32 -> bf16 hi/lo, K padded to 112 -------
        {
            const float* rb = res + (size_t)tix * TILE_M * RES_DIM;
            for (int i = tid; i < 128 * 32; i += THREADS) {
                int r = i >> 5, c4 = i & 31;
                if (c4 >= 28) continue;
                float4 v = make_float4(0.f, 0.f, 0.f, 0.f);
                if (c4 < 25) v = *(const float4*)(rb + r * RES_DIM + c4 * 4);
                uint16_t h0,l0,h1,l1,h2,l2,h3,l3;
                split_bf(v.x,h0,l0); split_bf(v.y,h1,l1);
                split_bf(v.z,h2,l2); split_bf(v.w,h3,l3);
                *(uint2*)(smem + AH_OFF + r * KSTR_B + c4 * 8) =
                    make_uint2((uint32_t)h1 << 16 | h0, (uint32_t)h3 << 16 | h2);
                *(uint2*)(smem + AL_OFF + r * KSTR_B + c4 * 8) =
                    make_uint2((uint32_t)l1 << 16 | l0, (uint32_t)l3 << 16 | l2);
            }
        }
        __syncthreads();

        // ---- Layer 1: [128x112] @ W1 -> 128x128, silu (warp tile 32x32) ---
        {
            float acc[8][4];
            layer_mma<2, 4, 7>(sb, AH_OFF, AL_OFF, B1H_OFF, B1L_OFF,
                               mbase, (w >> 2) * 32, lane, acc);
            __syncthreads();
            epi_store_bf<2, 4>(smem, MISC_B1, mbase, (w >> 2) * 32, g, t, acc);
        }
        __syncthreads();

        // ---- Layer 2: [128x128] @ W2 -> 128x64, silu (warp tile 32x16) ----
        {
            float acc[4][4];
            layer_mma<2, 2, 8>(sb, AH_OFF, AL_OFF, B2H_OFF, B2L_OFF,
                               mbase, (w >> 2) * 16, lane, acc);
            __syncthreads();
            epi_store_bf<2, 2>(smem, MISC_B2, mbase, (w >> 2) * 16, g, t, acc);
        }
        __syncthreads();

        // ---- Layer 3: [128x64] @ W3 -> 128x32, silu (warp tile 16x16) -----
        {
            float acc[2][4];
            layer_mma<1, 2, 4>(sb, AH_OFF, AL_OFF, B3H_OFF, B3L_OFF,
                               mbase3, (w >> 3) * 16, lane, acc);
            __syncthreads();   // all warps done reading A before fp32 overwrite
            float* h3 = (float*)(smem + AH_OFF);
            const int nbase = (w >> 3) * 16;
            #pragma unroll
            for (int nb = 0; nb < 2; nb++) {
                const float* cc = acc[nb];
                int col = nbase + nb * 8 + 2 * t;
                float bb0 = *(const float*)(smem + MISC_B3 + col * 4);
                float bb1 = *(const float*)(smem + MISC_B3 + (col + 1) * 4);
                int r0 = mbase3 + g;
                h3[r0 * H3_STRIDE + col]       = siluf(cc[0] + bb0);
                h3[r0 * H3_STRIDE + col + 1]   = siluf(cc[1] + bb1);
                h3[(r0+8) * H3_STRIDE + col]   = siluf(cc[2] + bb0);
                h3[(r0+8) * H3_STRIDE + col+1] = siluf(cc[3] + bb1);
            }
        }
        __syncthreads();

        // ---- Layer 4: dot with W4 -> raw ----------------------------------
        if (tid < TILE_M) {
            const float* h3 = (const float*)(smem + AH_OFF) + tid * H3_STRIDE;
            float accv = b4c;
            #pragma unroll
            for (int h = 0; h < 32; h++)
                accv = fmaf(h3[h], *(const float*)(smem + MISC_W4 + h * 4), accv);
            rawOut[(size_t)(tix * TILE_M + tid) * NCH + c] = accv;
        }
        __syncthreads();   // protect A region before next tile staging
    }
}

// ---------------------------------------------------------------------------
// Coupled fixed-point kernel
// ---------------------------------------------------------------------------
__global__ __launch_bounds__(256)
void chambers_couple_kernel(const float* __restrict__ raw,
                            const float* __restrict__ coupling,
                            const float* __restrict__ decay,
                            float* __restrict__ act)
{
    __shared__ float cd[NCH * NCH];
    int t = threadIdx.x;
    if (t < NCH * NCH) {
        int c = t / NCH, j = t % NCH;
        cd[t] = decay[c] * coupling[c * NCH + j] * CF_K;
    }
    __syncthreads();

    int b = blockIdx.x * blockDim.x + t;
    if (b >= BATCH) return;

    float r[NCH], a[NCH];
    #pragma unroll
    for (int c = 0; c < NCH; c++) r[c] = raw[(size_t)b * NCH + c];
    #pragma unroll
    for (int c = 0; c < NCH; c++) a[c] = sigmoidf_fast(r[c]);

    #pragma unroll
    for (int it = 0; it < 5; it++) {
        float d[NCH];
        #pragma unroll
        for (int j = 0; j < NCH; j++) d[j] = 0.0f;
        #pragma unroll
        for (int c = 0; c < NCH; c++)
            #pragma unroll
            for (int j = 0; j < NCH; j++)
                d[j] = fmaf(a[c], cd[c * NCH + j], d[j]);
        #pragma unroll
        for (int j = 0; j < NCH; j++) a[j] = sigmoidf_fast(r[j] + d[j]);
    }
    #pragma unroll
    for (int c = 0; c < NCH; c++) act[(size_t)b * NCH + c] = a[c];
}

// ---------------------------------------------------------------------------
// Launch
// ---------------------------------------------------------------------------
extern "C" void kernel_launch(void* const* d_in, const int* in_sizes, int n_in,
                              void* d_out, int out_size)
{
    const float* res      = (const float*)d_in[0];
    const float* W1       = (const float*)d_in[1];
    const float* b1       = (const float*)d_in[2];
    const float* W2       = (const float*)d_in[3];
    const float* b2       = (const float*)d_in[4];
    const float* W3       = (const float*)d_in[5];
    const float* b3       = (const float*)d_in[6];
    const float* W4       = (const float*)d_in[7];
    const float* b4       = (const float*)d_in[8];
    const float* coupling = (const float*)d_in[9];
    const float* decay    = (const float*)d_in[10];

    float* out = (float*)d_out;
    float* act = out;                          // [B, 6]
    float* raw = out + (size_t)BATCH * NCH;    // [B, 6]

    cudaFuncSetAttribute(chambers_mlp_hmma,
                         cudaFuncAttributeMaxDynamicSharedMemorySize, SMEM_BYTES);

    chambers_mlp_hmma<<<GRID_MLP, THREADS, SMEM_BYTES>>>(
        res, W1, b1, W2, b2, W3, b3, W4, b4, raw);

    chambers_couple_kernel<<<(BATCH + 255) / 256, 256>>>(raw, coupling, decay, act);
}

// round 13
// speedup vs baseline: 1.3245x; 1.0380x over previous
#include <cuda_runtime.h>
#include <cuda_bf16.h>
#include <cstdint>

// ---------------------------------------------------------------------------
// Problem constants
// ---------------------------------------------------------------------------
#define BATCH    131072
#define NCH      6
#define RES_DIM  100
#define CF_K     0.02f
#define TILE_M   128
#define THREADS  512
#define NTILES   (BATCH / TILE_M)     // 1024
#define CTAS_PER_CH 24
#define GRID_MLP (NCH * CTAS_PER_CH)  // 144

// K-strides (bytes): all 16-aligned, word-stride mod 32 in {20,4} -> LDSM
// 8-row phases hit all 32 banks exactly once.
#define KS1  208     // layer-1 operands: K=104 bf16 (100 data + 4 zero pad)
#define KS2  272     // K=128 operands (H1, W2^T)
#define KS3  144     // K=64 operands (H2, W3^T)

// ---------------------------------------------------------------------------
// SMEM layout (bytes)
// ---------------------------------------------------------------------------
#define A0H_OFF   0            // res hi [128 x 104] s208 = 26624 ; later H2 hi s144
#define A0L_OFF   26624        // res lo                         ; later H2 lo
#define H2H_OFF   0            // H2 hi [128 x 64] s144 = 18432 (inside A0)
#define H2L_OFF   18432
#define H1H_OFF   53248        // H1 hi [128 x 128] s272 = 34816
#define H1L_OFF   88064
#define H3F_OFF   53248        // H3 fp32 [128 x 33] = 16896 (inside A1, after L2 done)
#define B1H_OFF   122880       // W1^T hi [128 x 104] s208 = 26624
#define B1L_OFF   149504
#define B2H_OFF   176128       // W2^T hi [64 x 128] s272 = 17408
#define B2L_OFF   193536
#define B3H_OFF   210944       // W3^T hi [32 x 64] s144 = 4608
#define B3L_OFF   215552
#define MISC_B1   220160       // 128 f32
#define MISC_B2   220672       // 64 f32
#define MISC_B3   220928       // 32 f32
#define MISC_W4   221056       // 32 f32
#define SMEM_BYTES 221184
#define H3_STRIDE 33           // floats

// ---------------------------------------------------------------------------
// Helpers
// ---------------------------------------------------------------------------
__device__ __forceinline__ float sigmoidf_fast(float x) {
    return __fdividef(1.0f, 1.0f + __expf(-x));
}
__device__ __forceinline__ float siluf(float x) { return x * sigmoidf_fast(x); }

__device__ __forceinline__ void split_bf(float x, uint16_t& h, uint16_t& l) {
    __nv_bfloat16 hb = __float2bfloat16(x);
    float r = x - __bfloat162float(hb);
    __nv_bfloat16 lb = __float2bfloat16(r);
    h = *(uint16_t*)&hb;  l = *(uint16_t*)&lb;
}

__device__ __forceinline__ void mma16816(float c[4],
                                         uint32_t a0, uint32_t a1, uint32_t a2, uint32_t a3,
                                         uint32_t b0, uint32_t b1) {
    asm volatile(
        "mma.sync.aligned.m16n8k16.row.col.f32.bf16.bf16.f32 "
        "{%0,%1,%2,%3}, {%4,%5,%6,%7}, {%8,%9}, {%0,%1,%2,%3};"
        : "+f"(c[0]), "+f"(c[1]), "+f"(c[2]), "+f"(c[3])
        : "r"(a0), "r"(a1), "r"(a2), "r"(a3), "r"(b0), "r"(b1));
}
__device__ __forceinline__ void mma1688(float c[4],
                                        uint32_t a0, uint32_t a1, uint32_t b0) {
    asm volatile(
        "mma.sync.aligned.m16n8k8.row.col.f32.bf16.bf16.f32 "
        "{%0,%1,%2,%3}, {%4,%5}, {%6}, {%0,%1,%2,%3};"
        : "+f"(c[0]), "+f"(c[1]), "+f"(c[2]), "+f"(c[3])
        : "r"(a0), "r"(a1), "r"(b0));
}

__device__ __forceinline__ void ldsm_x4(uint32_t& r0, uint32_t& r1,
                                        uint32_t& r2, uint32_t& r3, uint32_t addr) {
    asm volatile("ldmatrix.sync.aligned.m8n8.x4.shared.b16 {%0,%1,%2,%3}, [%4];"
                 : "=r"(r0), "=r"(r1), "=r"(r2), "=r"(r3) : "r"(addr));
}
__device__ __forceinline__ void ldsm_x2(uint32_t& r0, uint32_t& r1, uint32_t addr) {
    asm volatile("ldmatrix.sync.aligned.m8n8.x2.shared.b16 {%0,%1}, [%2];"
                 : "=r"(r0), "=r"(r1) : "r"(addr));
}

// ---------------------------------------------------------------------------
// Layer MMA.  Warp tile [MBLK*16 x NBLK*8]; 3 products Ah*Bh + Ah*Bl + Al*Bh.
// KTAIL adds one k8 step at byte offset KSTEPS*32.
// ---------------------------------------------------------------------------
template<int MBLK, int NBLK, int KSTEPS, int KSTR, int KTAIL>
__device__ __forceinline__ void layer_mma(uint32_t sb,
                                          int aH, int aL, int bH, int bL,
                                          int mbase, int nbase, int lane,
                                          float (*acc)[4])
{
    #pragma unroll
    for (int i = 0; i < MBLK * NBLK; i++)
        #pragma unroll
        for (int j = 0; j < 4; j++) acc[i][j] = 0.0f;

    const uint32_t aRow = (uint32_t)(mbase + (lane & 15)) * KSTR + ((lane >> 4) << 4);
    const uint32_t aH0 = sb + aH + aRow;
    const uint32_t aL0 = sb + aL + aRow;
    const uint32_t bRow = (uint32_t)(nbase + ((lane & 16) >> 1) + (lane & 7)) * KSTR
                        + ((lane & 8) << 1);
    const uint32_t bH0 = sb + bH + bRow;
    const uint32_t bL0 = sb + bL + bRow;

    #pragma unroll
    for (int ks = 0; ks < KSTEPS; ks++) {
        const uint32_t ko = (uint32_t)ks * 32u;
        uint32_t ah[MBLK][4], al[MBLK][4];
        #pragma unroll
        for (int mb = 0; mb < MBLK; mb++) {
            ldsm_x4(ah[mb][0], ah[mb][1], ah[mb][2], ah[mb][3],
                    aH0 + (uint32_t)mb * 16 * KSTR + ko);
            ldsm_x4(al[mb][0], al[mb][1], al[mb][2], al[mb][3],
                    aL0 + (uint32_t)mb * 16 * KSTR + ko);
        }
        #pragma unroll
        for (int j = 0; j < NBLK / 2; j++) {
            uint32_t bh0, bh1, bh2, bh3, bl0, bl1, bl2, bl3;
            ldsm_x4(bh0, bh1, bh2, bh3, bH0 + (uint32_t)j * 16 * KSTR + ko);
            ldsm_x4(bl0, bl1, bl2, bl3, bL0 + (uint32_t)j * 16 * KSTR + ko);
            #pragma unroll
            for (int mb = 0; mb < MBLK; mb++) {
                float* c0 = acc[mb * NBLK + 2 * j];
                float* c1 = acc[mb * NBLK + 2 * j + 1];
                mma16816(c0, ah[mb][0], ah[mb][1], ah[mb][2], ah[mb][3], bh0, bh1);
                mma16816(c0, ah[mb][0], ah[mb][1], ah[mb][2], ah[mb][3], bl0, bl1);
                mma16816(c0, al[mb][0], al[mb][1], al[mb][2], al[mb][3], bh0, bh1);
                mma16816(c1, ah[mb][0], ah[mb][1], ah[mb][2], ah[mb][3], bh2, bh3);
                mma16816(c1, ah[mb][0], ah[mb][1], ah[mb][2], ah[mb][3], bl2, bl3);
                mma16816(c1, al[mb][0], al[mb][1], al[mb][2], al[mb][3], bh2, bh3);
            }
        }
    }

    if (KTAIL) {
        const uint32_t ko = (uint32_t)KSTEPS * 32u;
        const uint32_t aT = (uint32_t)(lane & 15) * KSTR + ko;
        uint32_t ah[MBLK][2], al[MBLK][2];
        #pragma unroll
        for (int mb = 0; mb < MBLK; mb++) {
            ldsm_x2(ah[mb][0], ah[mb][1], sb + aH + (uint32_t)(mbase + mb * 16) * KSTR + aT);
            ldsm_x2(al[mb][0], al[mb][1], sb + aL + (uint32_t)(mbase + mb * 16) * KSTR + aT);
        }
        #pragma unroll
        for (int j = 0; j < NBLK / 2; j++) {
            const uint32_t bT = (uint32_t)(nbase + j * 16 + (lane & 15)) * KSTR + ko;
            uint32_t bh0, bh1, bl0, bl1;
            ldsm_x2(bh0, bh1, sb + bH + bT);
            ldsm_x2(bl0, bl1, sb + bL + bT);
            #pragma unroll
            for (int mb = 0; mb < MBLK; mb++) {
                float* c0 = acc[mb * NBLK + 2 * j];
                float* c1 = acc[mb * NBLK + 2 * j + 1];
                mma1688(c0, ah[mb][0], ah[mb][1], bh0);
                mma1688(c0, ah[mb][0], ah[mb][1], bl0);
                mma1688(c0, al[mb][0], al[mb][1], bh0);
                mma1688(c1, ah[mb][0], ah[mb][1], bh1);
                mma1688(c1, ah[mb][0], ah[mb][1], bl1);
                mma1688(c1, al[mb][0], al[mb][1], bh1);
            }
        }
    }
}

// Epilogue: bias + silu, re-split to bf16 hi/lo, store at (dstH, dstL) stride DSTR.
template<int MBLK, int NBLK, int DSTR>
__device__ __forceinline__ void epi_store_bf(char* smem, int biasOff,
                                             int dstH, int dstL,
                                             int mbase, int nbase, int g, int t,
                                             float (*acc)[4])
{
    #pragma unroll
    for (int mb = 0; mb < MBLK; mb++) {
        #pragma unroll
        for (int nb = 0; nb < NBLK; nb++) {
            const float* c = acc[mb * NBLK + nb];
            int col = nbase + nb * 8 + 2 * t;
            float bb0 = *(const float*)(smem + biasOff + col * 4);
            float bb1 = *(const float*)(smem + biasOff + (col + 1) * 4);
            int r0 = mbase + mb * 16 + g;
            float x0 = siluf(c[0] + bb0), x1 = siluf(c[1] + bb1);
            float y0 = siluf(c[2] + bb0), y1 = siluf(c[3] + bb1);
            uint16_t h0,l0,h1,l1;
            split_bf(x0, h0, l0); split_bf(x1, h1, l1);
            *(uint32_t*)(smem + dstH + r0 * DSTR + col * 2) = (uint32_t)h1 << 16 | h0;
            *(uint32_t*)(smem + dstL + r0 * DSTR + col * 2) = (uint32_t)l1 << 16 | l0;
            split_bf(y0, h0, l0); split_bf(y1, h1, l1);
            *(uint32_t*)(smem + dstH + (r0+8) * DSTR + col * 2) = (uint32_t)h1 << 16 | h0;
            *(uint32_t*)(smem + dstL + (r0+8) * DSTR + col * 2) = (uint32_t)l1 << 16 | l0;
        }
    }
}

// ---------------------------------------------------------------------------
// MLP kernel: persistent, HMMA split-bf16, ping-pong buffers, 4 bars/tile
// ---------------------------------------------------------------------------
__global__ __launch_bounds__(THREADS, 1)
void chambers_mlp_hmma(const float* __restrict__ res,
                       const float* __restrict__ W1, const float* __restrict__ b1,
                       const float* __restrict__ W2, const float* __restrict__ b2,
                       const float* __restrict__ W3, const float* __restrict__ b3,
                       const float* __restrict__ W4, const float* __restrict__ b4,
                       float* __restrict__ rawOut)
{
    extern __shared__ char smem[];
    const uint32_t sb = (uint32_t)__cvta_generic_to_shared(smem);
    const int tid  = threadIdx.x;
    const int w    = tid >> 5;
    const int lane = tid & 31;
    const int g    = lane >> 2;
    const int t    = lane & 3;
    const int c    = blockIdx.x / CTAS_PER_CH;
    const int slot = blockIdx.x % CTAS_PER_CH;

    // ---- stage weights once -----------------------------------------------
    {
        const float* W1g = W1 + c * 12800;
        for (int i = tid; i < 128 * 104; i += THREADS) {
            int n = i / 104, k = i - n * 104;
            float x = (k < RES_DIM) ? W1g[k * 128 + n] : 0.0f;
            uint16_t h, l; split_bf(x, h, l);
            *(uint16_t*)(smem + B1H_OFF + n * KS1 + k * 2) = h;
            *(uint16_t*)(smem + B1L_OFF + n * KS1 + k * 2) = l;
        }
        const float* W2g = W2 + c * 8192;
        for (int i = tid; i < 64 * 128; i += THREADS) {
            int n = i >> 7, k = i & 127;
            uint16_t h, l; split_bf(W2g[k * 64 + n], h, l);
            *(uint16_t*)(smem + B2H_OFF + n * KS2 + k * 2) = h;
            *(uint16_t*)(smem + B2L_OFF + n * KS2 + k * 2) = l;
        }
        const float* W3g = W3 + c * 2048;
        for (int i = tid; i < 32 * 64; i += THREADS) {
            int n = i >> 6, k = i & 63;
            uint16_t h, l; split_bf(W3g[k * 32 + n], h, l);
            *(uint16_t*)(smem + B3H_OFF + n * KS3 + k * 2) = h;
            *(uint16_t*)(smem + B3L_OFF + n * KS3 + k * 2) = l;
        }
        if (tid < 128) *(float*)(smem + MISC_B1 + tid * 4) = b1[c * 128 + tid];
        if (tid < 64)  *(float*)(smem + MISC_B2 + tid * 4) = b2[c * 64 + tid];
        if (tid < 32)  *(float*)(smem + MISC_B3 + tid * 4) = b3[c * 32 + tid];
        if (tid < 32)  *(float*)(smem + MISC_W4 + tid * 4) = W4[c * 32 + tid];
    }
    const float b4c = b4[c];

    const int mbase  = (w & 3) * 32;      // layers 1-2: 4 m-groups x 32 rows
    const int mbase3 = (w & 7) * 16;      // layer 3: 8 m-groups x 16 rows

    // ---- prologue: stage first res tile (A0), then barrier ---------------
    {
        const float* rb = res + (size_t)slot * TILE_M * RES_DIM;
        for (int i = tid; i < 128 * 32; i += THREADS) {
            int r = i >> 5, c4 = i & 31;
            if (c4 >= 26) continue;
            float4 v = make_float4(0.f, 0.f, 0.f, 0.f);
            if (c4 < 25) v = *(const float4*)(rb + r * RES_DIM + c4 * 4);
            uint16_t h0,l0,h1,l1,h2,l2,h3,l3;
            split_bf(v.x,h0,l0); split_bf(v.y,h1,l1);
            split_bf(v.z,h2,l2); split_bf(v.w,h3,l3);
            *(uint2*)(smem + A0H_OFF + r * KS1 + c4 * 8) =
                make_uint2((uint32_t)h1 << 16 | h0, (uint32_t)h3 << 16 | h2);
            *(uint2*)(smem + A0L_OFF + r * KS1 + c4 * 8) =
                make_uint2((uint32_t)l1 << 16 | l0, (uint32_t)l3 << 16 | l2);
        }
    }
    __syncthreads();   // weights + first A0 ready

    for (int tix = slot; tix < NTILES; tix += CTAS_PER_CH) {
        // ---- Layer 1: A0[128x104] @ W1 -> H1 (A1), silu -------------------
        {
            float acc[8][4];
            layer_mma<2, 4, 6, KS1, 1>(sb, A0H_OFF, A0L_OFF, B1H_OFF, B1L_OFF,
                                       mbase, (w >> 2) * 32, lane, acc);
            epi_store_bf<2, 4, KS2>(smem, MISC_B1, H1H_OFF, H1L_OFF,
                                    mbase, (w >> 2) * 32, g, t, acc);
        }
        __syncthreads();   // H1 ready (also: everyone done reading A0)

        // ---- Layer 2: H1[128x128] @ W2 -> H2 (A0), silu -------------------
        {
            float acc[4][4];
            layer_mma<2, 2, 8, KS2, 0>(sb, H1H_OFF, H1L_OFF, B2H_OFF, B2L_OFF,
                                       mbase, (w >> 2) * 16, lane, acc);
            epi_store_bf<2, 2, KS3>(smem, MISC_B2, H2H_OFF, H2L_OFF,
                                    mbase, (w >> 2) * 16, g, t, acc);
        }
        __syncthreads();   // H2 ready (everyone done reading H1)

        // ---- Layer 3: H2[128x64] @ W3 -> H3 fp32 (A1 front), silu ---------
        {
            float acc[2][4];
            layer_mma<1, 2, 4, KS3, 0>(sb, H2H_OFF, H2L_OFF, B3H_OFF, B3L_OFF,
                                       mbase3, (w >> 3) * 16, lane, acc);
            float* h3 = (float*)(smem + H3F_OFF);
            const int nbase = (w >> 3) * 16;
            #pragma unroll
            for (int nb = 0; nb < 2; nb++) {
                const float* cc = acc[nb];
                int col = nbase + nb * 8 + 2 * t;
                float bb0 = *(const float*)(smem + MISC_B3 + col * 4);
                float bb1 = *(const float*)(smem + MISC_B3 + (col + 1) * 4);
                int r0 = mbase3 + g;
                h3[r0 * H3_STRIDE + col]       = siluf(cc[0] + bb0);
                h3[r0 * H3_STRIDE + col + 1]   = siluf(cc[1] + bb1);
                h3[(r0+8) * H3_STRIDE + col]   = siluf(cc[2] + bb0);
                h3[(r0+8) * H3_STRIDE + col+1] = siluf(cc[3] + bb1);
            }
        }
        __syncthreads();   // H3 ready (everyone done reading H2/A0)

        // ---- Layer 4 (warps 0-3)  ||  stage next res tile into A0 ---------
        if (tid < TILE_M) {
            const float* h3 = (const float*)(smem + H3F_OFF) + tid * H3_STRIDE;
            float accv = b4c;
            #pragma unroll
            for (int h = 0; h < 32; h++)
                accv = fmaf(h3[h], *(const float*)(smem + MISC_W4 + h * 4), accv);
            rawOut[(size_t)(tix * TILE_M + tid) * NCH + c] = accv;
        }
        int tn = tix + CTAS_PER_CH;
        if (tn < NTILES) {
            const float* rb = res + (size_t)tn * TILE_M * RES_DIM;
            for (int i = tid; i < 128 * 32; i += THREADS) {
                int r = i >> 5, c4 = i & 31;
                if (c4 >= 26) continue;
                float4 v = make_float4(0.f, 0.f, 0.f, 0.f);
                if (c4 < 25) v = *(const float4*)(rb + r * RES_DIM + c4 * 4);
                uint16_t h0,l0,h1,l1,h2,l2,h3,l3;
                split_bf(v.x,h0,l0); split_bf(v.y,h1,l1);
                split_bf(v.z,h2,l2); split_bf(v.w,h3,l3);
                *(uint2*)(smem + A0H_OFF + r * KS1 + c4 * 8) =
                    make_uint2((uint32_t)h1 << 16 | h0, (uint32_t)h3 << 16 | h2);
                *(uint2*)(smem + A0L_OFF + r * KS1 + c4 * 8) =
                    make_uint2((uint32_t)l1 << 16 | l0, (uint32_t)l3 << 16 | l2);
            }
        }
        __syncthreads();   // A0(next) ready; L4 reads of H3 done before next L1 epi
    }
}

// ---------------------------------------------------------------------------
// Coupled fixed-point kernel
// ---------------------------------------------------------------------------
__global__ __launch_bounds__(256)
void chambers_couple_kernel(const float* __restrict__ raw,
                            const float* __restrict__ coupling,
                            const float* __restrict__ decay,
                            float* __restrict__ act)
{
    __shared__ float cd[NCH * NCH];
    int t = threadIdx.x;
    if (t < NCH * NCH) {
        int c = t / NCH, j = t % NCH;
        cd[t] = decay[c] * coupling[c * NCH + j] * CF_K;
    }
    __syncthreads();

    int b = blockIdx.x * blockDim.x + t;
    if (b >= BATCH) return;

    float r[NCH], a[NCH];
    #pragma unroll
    for (int c = 0; c < NCH; c++) r[c] = raw[(size_t)b * NCH + c];
    #pragma unroll
    for (int c = 0; c < NCH; c++) a[c] = sigmoidf_fast(r[c]);

    #pragma unroll
    for (int it = 0; it < 5; it++) {
        float d[NCH];
        #pragma unroll
        for (int j = 0; j < NCH; j++) d[j] = 0.0f;
        #pragma unroll
        for (int c = 0; c < NCH; c++)
            #pragma unroll
            for (int j = 0; j < NCH; j++)
                d[j] = fmaf(a[c], cd[c * NCH + j], d[j]);
        #pragma unroll
        for (int j = 0; j < NCH; j++) a[j] = sigmoidf_fast(r[j] + d[j]);
    }
    #pragma unroll
    for (int c = 0; c < NCH; c++) act[(size_t)b * NCH + c] = a[c];
}

// ---------------------------------------------------------------------------
// Launch
// ---------------------------------------------------------------------------
extern "C" void kernel_launch(void* const* d_in, const int* in_sizes, int n_in,
                              void* d_out, int out_size)
{
    const float* res      = (const float*)d_in[0];
    const float* W1       = (const float*)d_in[1];
    const float* b1       = (const float*)d_in[2];
    const float* W2       = (const float*)d_in[3];
    const float* b2       = (const float*)d_in[4];
    const float* W3       = (const float*)d_in[5];
    const float* b3       = (const float*)d_in[6];
    const float* W4       = (const float*)d_in[7];
    const float* b4       = (const float*)d_in[8];
    const float* coupling = (const float*)d_in[9];
    const float* decay    = (const float*)d_in[10];

    float* out = (float*)d_out;
    float* act = out;                          // [B, 6]
    float* raw = out + (size_t)BATCH * NCH;    // [B, 6]

    cudaFuncSetAttribute(chambers_mlp_hmma,
                         cudaFuncAttributeMaxDynamicSharedMemorySize, SMEM_BYTES);

    chambers_mlp_hmma<<<GRID_MLP, THREADS, SMEM_BYTES>>>(
        res, W1, b1, W2, b2, W3, b3, W4, b4, raw);

    chambers_couple_kernel<<<(BATCH + 255) / 256, 256>>>(raw, coupling, decay, act);
}

// round 16
// speedup vs baseline: 1.3853x; 1.0458x over previous
#include <cuda_runtime.h>
#include <cuda_bf16.h>
#include <cstdint>

// ---------------------------------------------------------------------------
// Problem constants
// ---------------------------------------------------------------------------
#define BATCH    131072
#define NCH      6
#define RES_DIM  100
#define CF_K     0.02f
#define TILE_M   64                   // rows per warp-group tile
#define THREADS  512
#define NT64     (BATCH / TILE_M)     // 2048
#define CTAS_PER_CH 24
#define GRID_MLP (NCH * CTAS_PER_CH)  // 144
#define GSTEP    (CTAS_PER_CH * 2)    // 48 group streams per chamber

// K-strides (bytes): all 16-aligned, word-stride mod 32 in {20,4} -> LDSM
// 8-row phases hit all 32 banks exactly once.
#define KS1  208     // layer-1 operands: K=104 bf16 (100 data + 4 zero pad)
#define KS2  272     // K=128 operands (H1, W2^T)
#define KS3  144     // K=64 operands (H2, W3^T)

// ---------------------------------------------------------------------------
// SMEM layout (bytes)
// Per-group region (x2): A0 hi/lo (res, later H2), H1 hi/lo (later H3 fp32)
// ---------------------------------------------------------------------------
#define G_SIZE    61440
// within group: A0H +0 (64x208=13312), A0L +13312, H1H +26624 (64x272=17408),
//               H1L +44032 ; overlays: H2H +0 (64x144=9216), H2L +9216,
//               H3F +26624 (64x33x4=8448)
#define B1H_OFF   122880       // W1^T hi [128 x 104] s208 = 26624
#define B1L_OFF   149504
#define B2H_OFF   176128       // W2^T hi [64 x 128] s272 = 17408
#define B2L_OFF   193536
#define B3H_OFF   210944       // W3^T hi [32 x 64] s144 = 4608
#define B3L_OFF   215552
#define MISC_B1   220160       // 128 f32
#define MISC_B2   220672       // 64 f32
#define MISC_B3   220928       // 32 f32
#define MISC_W4   221056       // 32 f32
#define SMEM_BYTES 221184
#define H3_STRIDE 33           // floats

// ---------------------------------------------------------------------------
// Helpers
// ---------------------------------------------------------------------------
__device__ __forceinline__ float sigmoidf_fast(float x) {
    return __fdividef(1.0f, 1.0f + __expf(-x));
}
__device__ __forceinline__ float siluf(float x) { return x * sigmoidf_fast(x); }

__device__ __forceinline__ void split_bf(float x, uint16_t& h, uint16_t& l) {
    __nv_bfloat16 hb = __float2bfloat16(x);
    float r = x - __bfloat162float(hb);
    __nv_bfloat16 lb = __float2bfloat16(r);
    h = *(uint16_t*)&hb;  l = *(uint16_t*)&lb;
}

__device__ __forceinline__ void mma16816(float c[4],
                                         uint32_t a0, uint32_t a1, uint32_t a2, uint32_t a3,
                                         uint32_t b0, uint32_t b1) {
    asm volatile(
        "mma.sync.aligned.m16n8k16.row.col.f32.bf16.bf16.f32 "
        "{%0,%1,%2,%3}, {%4,%5,%6,%7}, {%8,%9}, {%0,%1,%2,%3};"
        : "+f"(c[0]), "+f"(c[1]), "+f"(c[2]), "+f"(c[3])
        : "r"(a0), "r"(a1), "r"(a2), "r"(a3), "r"(b0), "r"(b1));
}
__device__ __forceinline__ void mma1688(float c[4],
                                        uint32_t a0, uint32_t a1, uint32_t b0) {
    asm volatile(
        "mma.sync.aligned.m16n8k8.row.col.f32.bf16.bf16.f32 "
        "{%0,%1,%2,%3}, {%4,%5}, {%6}, {%0,%1,%2,%3};"
        : "+f"(c[0]), "+f"(c[1]), "+f"(c[2]), "+f"(c[3])
        : "r"(a0), "r"(a1), "r"(b0));
}

__device__ __forceinline__ void ldsm_x4(uint32_t& r0, uint32_t& r1,
                                        uint32_t& r2, uint32_t& r3, uint32_t addr) {
    asm volatile("ldmatrix.sync.aligned.m8n8.x4.shared.b16 {%0,%1,%2,%3}, [%4];"
                 : "=r"(r0), "=r"(r1), "=r"(r2), "=r"(r3) : "r"(addr));
}
__device__ __forceinline__ void ldsm_x2(uint32_t& r0, uint32_t& r1, uint32_t addr) {
    asm volatile("ldmatrix.sync.aligned.m8n8.x2.shared.b16 {%0,%1}, [%2];"
                 : "=r"(r0), "=r"(r1) : "r"(addr));
}

// named barrier for one 8-warp group (256 threads); ids 1 and 2
__device__ __forceinline__ void barg(int grp) {
    asm volatile("bar.sync %0, 256;" :: "r"(grp + 1) : "memory");
}

// ---------------------------------------------------------------------------
// Layer MMA.  Warp tile [MBLK*16 x NBLK*8]; 3 products Ah*Bh + Ah*Bl + Al*Bh.
// KTAIL adds one k8 step at byte offset KSTEPS*32.
// ---------------------------------------------------------------------------
template<int MBLK, int NBLK, int KSTEPS, int KSTR, int KTAIL>
__device__ __forceinline__ void layer_mma(uint32_t sb,
                                          int aH, int aL, int bH, int bL,
                                          int mbase, int nbase, int lane,
                                          float (*acc)[4])
{
    #pragma unroll
    for (int i = 0; i < MBLK * NBLK; i++)
        #pragma unroll
        for (int j = 0; j < 4; j++) acc[i][j] = 0.0f;

    const uint32_t aRow = (uint32_t)(mbase + (lane & 15)) * KSTR + ((lane >> 4) << 4);
    const uint32_t aH0 = sb + aH + aRow;
    const uint32_t aL0 = sb + aL + aRow;
    const uint32_t bRow = (uint32_t)(nbase + ((lane & 16) >> 1) + (lane & 7)) * KSTR
                        + ((lane & 8) << 1);
    const uint32_t bH0 = sb + bH + bRow;
    const uint32_t bL0 = sb + bL + bRow;

    #pragma unroll
    for (int ks = 0; ks < KSTEPS; ks++) {
        const uint32_t ko = (uint32_t)ks * 32u;
        uint32_t ah[MBLK][4], al[MBLK][4];
        #pragma unroll
        for (int mb = 0; mb < MBLK; mb++) {
            ldsm_x4(ah[mb][0], ah[mb][1], ah[mb][2], ah[mb][3],
                    aH0 + (uint32_t)mb * 16 * KSTR + ko);
            ldsm_x4(al[mb][0], al[mb][1], al[mb][2], al[mb][3],
                    aL0 + (uint32_t)mb * 16 * KSTR + ko);
        }
        #pragma unroll
        for (int j = 0; j < NBLK / 2; j++) {
            uint32_t bh0, bh1, bh2, bh3, bl0, bl1, bl2, bl3;
            ldsm_x4(bh0, bh1, bh2, bh3, bH0 + (uint32_t)j * 16 * KSTR + ko);
            ldsm_x4(bl0, bl1, bl2, bl3, bL0 + (uint32_t)j * 16 * KSTR + ko);
            #pragma unroll
            for (int mb = 0; mb < MBLK; mb++) {
                float* c0 = acc[mb * NBLK + 2 * j];
                float* c1 = acc[mb * NBLK + 2 * j + 1];
                mma16816(c0, ah[mb][0], ah[mb][1], ah[mb][2], ah[mb][3], bh0, bh1);
                mma16816(c0, ah[mb][0], ah[mb][1], ah[mb][2], ah[mb][3], bl0, bl1);
                mma16816(c0, al[mb][0], al[mb][1], al[mb][2], al[mb][3], bh0, bh1);
                mma16816(c1, ah[mb][0], ah[mb][1], ah[mb][2], ah[mb][3], bh2, bh3);
                mma16816(c1, ah[mb][0], ah[mb][1], ah[mb][2], ah[mb][3], bl2, bl3);
                mma16816(c1, al[mb][0], al[mb][1], al[mb][2], al[mb][3], bh2, bh3);
            }
        }
    }

    if (KTAIL) {
        const uint32_t ko = (uint32_t)KSTEPS * 32u;
        const uint32_t aT = (uint32_t)(lane & 15) * KSTR + ko;
        uint32_t ah[MBLK][2], al[MBLK][2];
        #pragma unroll
        for (int mb = 0; mb < MBLK; mb++) {
            ldsm_x2(ah[mb][0], ah[mb][1], sb + aH + (uint32_t)(mbase + mb * 16) * KSTR + aT);
            ldsm_x2(al[mb][0], al[mb][1], sb + aL + (uint32_t)(mbase + mb * 16) * KSTR + aT);
        }
        #pragma unroll
        for (int j = 0; j < NBLK / 2; j++) {
            const uint32_t bT = (uint32_t)(nbase + j * 16 + (lane & 15)) * KSTR + ko;
            uint32_t bh0, bh1, bl0, bl1;
            ldsm_x2(bh0, bh1, sb + bH + bT);
            ldsm_x2(bl0, bl1, sb + bL + bT);
            #pragma unroll
            for (int mb = 0; mb < MBLK; mb++) {
                float* c0 = acc[mb * NBLK + 2 * j];
                float* c1 = acc[mb * NBLK + 2 * j + 1];
                mma1688(c0, ah[mb][0], ah[mb][1], bh0);
                mma1688(c0, ah[mb][0], ah[mb][1], bl0);
                mma1688(c0, al[mb][0], al[mb][1], bh0);
                mma1688(c1, ah[mb][0], ah[mb][1], bh1);
                mma1688(c1, ah[mb][0], ah[mb][1], bl1);
                mma1688(c1, al[mb][0], al[mb][1], bh1);
            }
        }
    }
}

// Epilogue: bias + silu, re-split to bf16 hi/lo, store at (dstH, dstL) stride DSTR.
template<int MBLK, int NBLK, int DSTR>
__device__ __forceinline__ void epi_store_bf(char* smem, int biasOff,
                                             int dstH, int dstL,
                                             int mbase, int nbase, int g, int t,
                                             float (*acc)[4])
{
    #pragma unroll
    for (int mb = 0; mb < MBLK; mb++) {
        #pragma unroll
        for (int nb = 0; nb < NBLK; nb++) {
            const float* c = acc[mb * NBLK + nb];
            int col = nbase + nb * 8 + 2 * t;
            float bb0 = *(const float*)(smem + biasOff + col * 4);
            float bb1 = *(const float*)(smem + biasOff + (col + 1) * 4);
            int r0 = mbase + mb * 16 + g;
            float x0 = siluf(c[0] + bb0), x1 = siluf(c[1] + bb1);
            float y0 = siluf(c[2] + bb0), y1 = siluf(c[3] + bb1);
            uint16_t h0,l0,h1,l1;
            split_bf(x0, h0, l0); split_bf(x1, h1, l1);
            *(uint32_t*)(smem + dstH + r0 * DSTR + col * 2) = (uint32_t)h1 << 16 | h0;
            *(uint32_t*)(smem + dstL + r0 * DSTR + col * 2) = (uint32_t)l1 << 16 | l0;
            split_bf(y0, h0, l0); split_bf(y1, h1, l1);
            *(uint32_t*)(smem + dstH + (r0+8) * DSTR + col * 2) = (uint32_t)h1 << 16 | h0;
            *(uint32_t*)(smem + dstL + (r0+8) * DSTR + col * 2) = (uint32_t)l1 << 16 | l0;
        }
    }
}

// stage a 64-row res tile (fp32 -> bf16 hi/lo), 256 threads of one group
__device__ __forceinline__ void stage_res(char* smem, int a0h, int a0l,
                                          const float* rb, int tid_g)
{
    for (int i = tid_g; i < 64 * 32; i += 256) {
        int r = i >> 5, c4 = i & 31;
        if (c4 >= 26) continue;
        float4 v = make_float4(0.f, 0.f, 0.f, 0.f);
        if (c4 < 25) v = *(const float4*)(rb + r * RES_DIM + c4 * 4);
        uint16_t h0,l0,h1,l1,h2,l2,h3,l3;
        split_bf(v.x,h0,l0); split_bf(v.y,h1,l1);
        split_bf(v.z,h2,l2); split_bf(v.w,h3,l3);
        *(uint2*)(smem + a0h + r * KS1 + c4 * 8) =
            make_uint2((uint32_t)h1 << 16 | h0, (uint32_t)h3 << 16 | h2);
        *(uint2*)(smem + a0l + r * KS1 + c4 * 8) =
            make_uint2((uint32_t)l1 << 16 | l0, (uint32_t)l3 << 16 | l2);
    }
}

// ---------------------------------------------------------------------------
// MLP kernel: persistent, HMMA split-bf16, TWO independent 8-warp groups
// per CTA (each its own 64-row tile stream), weights shared in SMEM.
// ---------------------------------------------------------------------------
__global__ __launch_bounds__(THREADS, 1)
void chambers_mlp_hmma(const float* __restrict__ res,
                       const float* __restrict__ W1, const float* __restrict__ b1,
                       const float* __restrict__ W2, const float* __restrict__ b2,
                       const float* __restrict__ W3, const float* __restrict__ b3,
                       const float* __restrict__ W4, const float* __restrict__ b4,
                       float* __restrict__ rawOut)
{
    extern __shared__ char smem[];
    const uint32_t sb = (uint32_t)__cvta_generic_to_shared(smem);
    const int tid  = threadIdx.x;
    const int w    = tid >> 5;
    const int lane = tid & 31;
    const int g    = lane >> 2;
    const int t    = lane & 3;
    const int grp  = w >> 3;          // warp-group 0 / 1
    const int wg   = w & 7;           // warp within group
    const int tid_g = tid & 255;      // thread within group
    const int c    = blockIdx.x / CTAS_PER_CH;
    const int slot = blockIdx.x % CTAS_PER_CH;

    // ---- stage weights once (all 512 threads) -----------------------------
    {
        const float* W1g = W1 + c * 12800;
        for (int i = tid; i < 128 * 104; i += THREADS) {
            int n = i / 104, k = i - n * 104;
            float x = (k < RES_DIM) ? W1g[k * 128 + n] : 0.0f;
            uint16_t h, l; split_bf(x, h, l);
            *(uint16_t*)(smem + B1H_OFF + n * KS1 + k * 2) = h;
            *(uint16_t*)(smem + B1L_OFF + n * KS1 + k * 2) = l;
        }
        const float* W2g = W2 + c * 8192;
        for (int i = tid; i < 64 * 128; i += THREADS) {
            int n = i >> 7, k = i & 127;
            uint16_t h, l; split_bf(W2g[k * 64 + n], h, l);
            *(uint16_t*)(smem + B2H_OFF + n * KS2 + k * 2) = h;
            *(uint16_t*)(smem + B2L_OFF + n * KS2 + k * 2) = l;
        }
        const float* W3g = W3 + c * 2048;
        for (int i = tid; i < 32 * 64; i += THREADS) {
            int n = i >> 6, k = i & 63;
            uint16_t h, l; split_bf(W3g[k * 32 + n], h, l);
            *(uint16_t*)(smem + B3H_OFF + n * KS3 + k * 2) = h;
            *(uint16_t*)(smem + B3L_OFF + n * KS3 + k * 2) = l;
        }
        if (tid < 128) *(float*)(smem + MISC_B1 + tid * 4) = b1[c * 128 + tid];
        if (tid < 64)  *(float*)(smem + MISC_B2 + tid * 4) = b2[c * 64 + tid];
        if (tid < 32)  *(float*)(smem + MISC_B3 + tid * 4) = b3[c * 32 + tid];
        if (tid < 32)  *(float*)(smem + MISC_W4 + tid * 4) = W4[c * 32 + tid];
    }
    const float b4c = b4[c];
    __syncthreads();   // weights visible to both groups; groups diverge after

    // per-group SMEM offsets
    const int A0H = grp * G_SIZE;
    const int A0L = A0H + 13312;
    const int H1H = A0H + 26624;
    const int H1L = A0H + 44032;
    const int H2H = A0H;              // overlays A0 (L3 reads after L2 bar)
    const int H2L = A0H + 9216;
    const int H3F = A0H + 26624;      // overlays H1 (fp32 scratch)

    // warp maps within the 64-row group tile
    const int mb12 = (wg & 1) * 32;           // L1/L2: 2 m-groups x 32 rows
    const int nb1  = (wg >> 1) * 32;          // L1: 4 n-groups x 32 cols
    const int nb2  = (wg >> 1) * 16;          // L2: 4 n-groups x 16 cols
    const int mb3  = (wg & 3) * 16;           // L3: 4 m-groups x 16 rows
    const int nb3  = (wg >> 2) * 16;          // L3: 2 n-groups x 16 cols

    const int start = slot * 2 + grp;

    // ---- prologue: stage first tile for this group ------------------------
    stage_res(smem, A0H, A0L, res + (size_t)start * TILE_M * RES_DIM, tid_g);
    barg(grp);

    for (int tix = start; tix < NT64; tix += GSTEP) {
        // ---- Layer 1: A0[64x104] @ W1 -> H1[64x128], silu -----------------
        {
            float acc[8][4];
            layer_mma<2, 4, 6, KS1, 1>(sb, A0H, A0L, B1H_OFF, B1L_OFF,
                                       mb12, nb1, lane, acc);
            epi_store_bf<2, 4, KS2>(smem, MISC_B1, H1H, H1L, mb12, nb1, g, t, acc);
        }
        barg(grp);   // H1 ready; A0 reads done

        // ---- Layer 2: H1[64x128] @ W2 -> H2[64x64] (A0 region), silu ------
        {
            float acc[4][4];
            layer_mma<2, 2, 8, KS2, 0>(sb, H1H, H1L, B2H_OFF, B2L_OFF,
                                       mb12, nb2, lane, acc);
            epi_store_bf<2, 2, KS3>(smem, MISC_B2, H2H, H2L, mb12, nb2, g, t, acc);
        }
        barg(grp);   // H2 ready; H1 reads done

        // ---- Layer 3: H2[64x64] @ W3 -> H3 fp32 (H1 region), silu ---------
        {
            float acc[2][4];
            layer_mma<1, 2, 4, KS3, 0>(sb, H2H, H2L, B3H_OFF, B3L_OFF,
                                       mb3, nb3, lane, acc);
            float* h3 = (float*)(smem + H3F);
            #pragma unroll
            for (int nb = 0; nb < 2; nb++) {
                const float* cc = acc[nb];
                int col = nb3 + nb * 8 + 2 * t;
                float bb0 = *(const float*)(smem + MISC_B3 + col * 4);
                float bb1 = *(const float*)(smem + MISC_B3 + (col + 1) * 4);
                int r0 = mb3 + g;
                h3[r0 * H3_STRIDE + col]       = siluf(cc[0] + bb0);
                h3[r0 * H3_STRIDE + col + 1]   = siluf(cc[1] + bb1);
                h3[(r0+8) * H3_STRIDE + col]   = siluf(cc[2] + bb0);
                h3[(r0+8) * H3_STRIDE + col+1] = siluf(cc[3] + bb1);
            }
        }
        barg(grp);   // H3 ready; H2 (A0) reads done

        // ---- Layer 4 (first 2 warps of group) || stage next tile into A0 --
        if (tid_g < TILE_M) {
            const float* h3 = (const float*)(smem + H3F) + tid_g * H3_STRIDE;
            float accv = b4c;
            #pragma unroll
            for (int h = 0; h < 32; h++)
                accv = fmaf(h3[h], *(const float*)(smem + MISC_W4 + h * 4), accv);
            rawOut[(size_t)(tix * TILE_M + tid_g) * NCH + c] = accv;
        }
        int tn = tix + GSTEP;
        if (tn < NT64)
            stage_res(smem, A0H, A0L, res + (size_t)tn * TILE_M * RES_DIM, tid_g);
        barg(grp);   // A0(next) ready; H3 reads done before next L1 epilogue
    }
}

// ---------------------------------------------------------------------------
// Coupled fixed-point kernel
// ---------------------------------------------------------------------------
__global__ __launch_bounds__(256)
void chambers_couple_kernel(const float* __restrict__ raw,
                            const float* __restrict__ coupling,
                            const float* __restrict__ decay,
                            float* __restrict__ act)
{
    __shared__ float cd[NCH * NCH];
    int t = threadIdx.x;
    if (t < NCH * NCH) {
        int c = t / NCH, j = t % NCH;
        cd[t] = decay[c] * coupling[c * NCH + j] * CF_K;
    }
    __syncthreads();

    int b = blockIdx.x * blockDim.x + t;
    if (b >= BATCH) return;

    float r[NCH], a[NCH];
    #pragma unroll
    for (int c = 0; c < NCH; c++) r[c] = raw[(size_t)b * NCH + c];
    #pragma unroll
    for (int c = 0; c < NCH; c++) a[c] = sigmoidf_fast(r[c]);

    #pragma unroll
    for (int it = 0; it < 5; it++) {
        float d[NCH];
        #pragma unroll
        for (int j = 0; j < NCH; j++) d[j] = 0.0f;
        #pragma unroll
        for (int c = 0; c < NCH; c++)
            #pragma unroll
            for (int j = 0; j < NCH; j++)
                d[j] = fmaf(a[c], cd[c * NCH + j], d[j]);
        #pragma unroll
        for (int j = 0; j < NCH; j++) a[j] = sigmoidf_fast(r[j] + d[j]);
    }
    #pragma unroll
    for (int c = 0; c < NCH; c++) act[(size_t)b * NCH + c] = a[c];
}

// ---------------------------------------------------------------------------
// Launch
// ---------------------------------------------------------------------------
extern "C" void kernel_launch(void* const* d_in, const int* in_sizes, int n_in,
                              void* d_out, int out_size)
{
    const float* res      = (const float*)d_in[0];
    const float* W1       = (const float*)d_in[1];
    const float* b1       = (const float*)d_in[2];
    const float* W2       = (const float*)d_in[3];
    const float* b2       = (const float*)d_in[4];
    const float* W3       = (const float*)d_in[5];
    const float* b3       = (const float*)d_in[6];
    const float* W4       = (const float*)d_in[7];
    const float* b4       = (const float*)d_in[8];
    const float* coupling = (const float*)d_in[9];
    const float* decay    = (const float*)d_in[10];

    float* out = (float*)d_out;
    float* act = out;                          // [B, 6]
    float* raw = out + (size_t)BATCH * NCH;    // [B, 6]

    cudaFuncSetAttribute(chambers_mlp_hmma,
                         cudaFuncAttributeMaxDynamicSharedMemorySize, SMEM_BYTES);

    chambers_mlp_hmma<<<GRID_MLP, THREADS, SMEM_BYTES>>>(
        res, W1, b1, W2, b2, W3, b3, W4, b4, raw);

    chambers_couple_kernel<<<(BATCH + 255) / 256, 256>>>(raw, coupling, decay, act);
}